// round 15
// baseline (speedup 1.0000x reference)
#include <cuda_runtime.h>
#include <cstdint>

// WKV (RWKV v4) — warp-parallel weighted scan, thread-serial-4, small-block
// stagger variant: 256-thread blocks, 4 blocks/SM = 4 independent load
// streams per SM (R4's proven recipe for driving DRAM), single pass
// (k,v read once, y written once = 192 MB floor).
//
//   state_t = lam*state_{t-1} + e^{k_t}(v_t, 1),  lam = exp(-exp(td[c]))
//   y_t = (A_{t-1} + e^u e^{k_t} v_t) / (B_{t-1} + e^u e^{k_t})
//
// Block = 256 thr = 8 warps = 8 channels x full T; warp = channel; each
// thread owns 4 consecutive timesteps (warp covers 128 t per tile).
// smem channel-major [8][132] (pad 132 -> transpose scalar STS/LDS banks
// (16cg + 4i + lt) mod 32 cover all 32 banks = conflict-free; scan LDS.128
// and y STS.128 conflict-free). Loads LDG.128 -> registers -> STS,
// pipelined one tile ahead; 32B sectors fully used (no traffic inflation).

constexpr int CPB     = 8;            // channels per block == warps
constexpr int TS      = 128;          // timesteps per tile
constexpr int STR     = 132;          // floats per channel row
constexpr int THREADS = 256;
constexpr int GRID    = 2048;
constexpr int ARR_F   = CPB * STR;    // floats per array buffer
// smem: k[2] | v[2] | y[1] = 21120 B -> 4 blocks/SM = 84 KB
constexpr int SMEM_BYTES = 5 * ARR_F * (int)sizeof(float);

__device__ __forceinline__ void stcs4(float* p, float4 v) {
    asm volatile("st.global.cs.v4.f32 [%0], {%1, %2, %3, %4};\n"
                 :: "l"(p), "f"(v.x), "f"(v.y), "f"(v.z), "f"(v.w) : "memory");
}
__device__ __forceinline__ void stcs(float* p, float v) {
    asm volatile("st.global.cs.f32 [%0], %1;\n" :: "l"(p), "f"(v) : "memory");
}
__device__ __forceinline__ float4 ldcs4(const float* p) {
    float4 v;
    asm volatile("ld.global.cs.v4.f32 {%0, %1, %2, %3}, [%4];\n"
                 : "=f"(v.x), "=f"(v.y), "=f"(v.z), "=f"(v.w) : "l"(p));
    return v;
}

__device__ __forceinline__ int read_dim(const void* p) {
    int i = *reinterpret_cast<const int*>(p);
    if (i >= 1 && i <= (1 << 20)) return i;
    float f = *reinterpret_cast<const float*>(p);
    int fi = (int)f;
    return (fi >= 1) ? fi : 1;
}

__global__ __launch_bounds__(THREADS, 4)
void wkv_warpscan_kernel(const void* __restrict__ seqlen_p,
                         const float* __restrict__ td,
                         const float* __restrict__ tf,
                         const float* __restrict__ kg,
                         const float* __restrict__ vg,
                         float* __restrict__ out,
                         int C, long long BTC)
{
    extern __shared__ float smem[];
    float* skb[2] = { smem,              smem + ARR_F };
    float* svb[2] = { smem + 2 * ARR_F,  smem + 3 * ARR_F };
    float* sy     =   smem + 4 * ARR_F;

    const int tid  = threadIdx.x;
    const int w    = tid >> 5;        // warp == local channel (0..7)
    const int lane = tid & 31;
    const int lt   = tid >> 1;        // 0..127 : timestep row for ld/st
    const int cg   = tid & 1;         // 0..1   : 4-channel group

    const int T = read_dim(seqlen_p);
    const long long BT = BTC / C;
    const int B = (int)(BT / T);
    const int ctiles = (C + CPB - 1) / CPB;
    const int nrows  = B * ctiles;
    const int ntiles = (T + TS - 1) / TS;
    const unsigned FULL = 0xffffffffu;

    const bool vec_ok = ((C & 7) == 0) &&
                        ((((uintptr_t)kg)  & 15) == 0) &&
                        ((((uintptr_t)vg)  & 15) == 0) &&
                        ((((uintptr_t)out) & 15) == 0);

    for (int row = blockIdx.x; row < nrows; row += gridDim.x) {
        const int b  = row / ctiles;
        const int c0 = (row % ctiles) * CPB;
        const float* kb = kg + (long long)b * T * C;
        const float* vb = vg + (long long)b * T * C;
        float* ob = out + (long long)b * T * C;

        const int  c      = c0 + w;
        const bool cvalid = (c < C);
        const float ew  = cvalid ? __expf(td[c]) : 0.f;   // e^{td}
        const float eu  = cvalid ? __expf(tf[c]) : 0.f;   // e^{tf}
        const float lam = __expf(-ew);                    // exp(-e^{td})
        const float l2   = lam * lam;
        const float lam4 = l2 * l2;                       // KS base weight
        const float w1 = lam4, w2 = w1 * w1, w4 = w2 * w2,
                    w8 = w4 * w4, w16 = w8 * w8;
        const float lam128 = w16 * w16;                   // lam^128
        const float lam4lane = __expf(-4.f * (float)lane * ew);  // lam^{4lane}

        float SA = 0.f, SB = 0.f;                         // running seed

        float4 kR, vR;                                    // staged next tile

        auto ldg_tile = [&](int ti) {
            int gt = ti * TS + lt; if (gt >= T) gt = T - 1;
            if (vec_ok) {
                const long long go = (long long)gt * C + c0 + cg * 4;
                kR = ldcs4(kb + go);
                vR = ldcs4(vb + go);
            } else {
                float kk[4], vv[4];
                #pragma unroll
                for (int i = 0; i < 4; ++i) {
                    const int gc = c0 + cg * 4 + i;
                    kk[i] = (gc < C) ? kb[(long long)gt * C + gc] : 0.f;
                    vv[i] = (gc < C) ? vb[(long long)gt * C + gc] : 0.f;
                }
                kR = make_float4(kk[0], kk[1], kk[2], kk[3]);
                vR = make_float4(vv[0], vv[1], vv[2], vv[3]);
            }
        };
        auto sts_tile = [&](int buf) {  // transpose registers -> [c][t]
            float* dk = skb[buf];
            float* dv = svb[buf];
            dk[(cg * 4 + 0) * STR + lt] = kR.x;
            dk[(cg * 4 + 1) * STR + lt] = kR.y;
            dk[(cg * 4 + 2) * STR + lt] = kR.z;
            dk[(cg * 4 + 3) * STR + lt] = kR.w;
            dv[(cg * 4 + 0) * STR + lt] = vR.x;
            dv[(cg * 4 + 1) * STR + lt] = vR.y;
            dv[(cg * 4 + 2) * STR + lt] = vR.z;
            dv[(cg * 4 + 3) * STR + lt] = vR.w;
        };

        // ---- prolog: fill buffer 0, stage tile 1 in registers ----
        ldg_tile(0);
        sts_tile(0);
        if (ntiles > 1) ldg_tile(1);
        __syncthreads();

        for (int ti = 0; ti < ntiles; ++ti) {
            const int buf = ti & 1;
            const int t0  = ti * TS;

            // ---- scan: one LDS.128 per array, conflict-free ----
            const float* tk = skb[buf] + w * STR + 4 * lane;
            const float* tv = svb[buf] + w * STR + 4 * lane;
            const float4 kq = *reinterpret_cast<const float4*>(tk);
            const float4 vq = *reinterpret_cast<const float4*>(tv);

            const int tg = t0 + 4 * lane;
            const float ek0 = (tg + 0 < T) ? __expf(kq.x) : 0.f;
            const float ek1 = (tg + 1 < T) ? __expf(kq.y) : 0.f;
            const float ek2 = (tg + 2 < T) ? __expf(kq.z) : 0.f;
            const float ek3 = (tg + 3 < T) ? __expf(kq.w) : 0.f;
            const float uA0 = ek0 * vq.x, uA1 = ek1 * vq.y;
            const float uA2 = ek2 * vq.z, uA3 = ek3 * vq.w;

            // Thread-local inclusive totals (4 steps).
            float IA = uA0, IB = ek0;
            IA = fmaf(lam, IA, uA1);  IB = fmaf(lam, IB, ek1);
            IA = fmaf(lam, IA, uA2);  IB = fmaf(lam, IB, ek2);
            IA = fmaf(lam, IA, uA3);  IB = fmaf(lam, IB, ek3);

            // Kogge-Stone over lanes, weight lam^4.
            float a, bb;
            a = __shfl_up_sync(FULL, IA, 1);  bb = __shfl_up_sync(FULL, IB, 1);
            if (lane >= 1)  { IA = fmaf(w1,  a, IA); IB = fmaf(w1,  bb, IB); }
            a = __shfl_up_sync(FULL, IA, 2);  bb = __shfl_up_sync(FULL, IB, 2);
            if (lane >= 2)  { IA = fmaf(w2,  a, IA); IB = fmaf(w2,  bb, IB); }
            a = __shfl_up_sync(FULL, IA, 4);  bb = __shfl_up_sync(FULL, IB, 4);
            if (lane >= 4)  { IA = fmaf(w4,  a, IA); IB = fmaf(w4,  bb, IB); }
            a = __shfl_up_sync(FULL, IA, 8);  bb = __shfl_up_sync(FULL, IB, 8);
            if (lane >= 8)  { IA = fmaf(w8,  a, IA); IB = fmaf(w8,  bb, IB); }
            a = __shfl_up_sync(FULL, IA, 16); bb = __shfl_up_sync(FULL, IB, 16);
            if (lane >= 16) { IA = fmaf(w16, a, IA); IB = fmaf(w16, bb, IB); }

            float EA = __shfl_up_sync(FULL, IA, 1);
            float EB = __shfl_up_sync(FULL, IB, 1);
            if (lane == 0) { EA = 0.f; EB = 0.f; }

            // State just before this thread's first element.
            float stA = fmaf(lam4lane, SA, EA);
            float stB = fmaf(lam4lane, SB, EB);

            // Re-serialized emit of 4 timesteps.
            float4 yq;
            float eku;
            eku  = eu * ek0;
            yq.x = __fdividef(fmaf(eku, vq.x, stA), stB + eku);
            stA  = fmaf(lam, stA, uA0);  stB = fmaf(lam, stB, ek0);
            eku  = eu * ek1;
            yq.y = __fdividef(fmaf(eku, vq.y, stA), stB + eku);
            stA  = fmaf(lam, stA, uA1);  stB = fmaf(lam, stB, ek1);
            eku  = eu * ek2;
            yq.z = __fdividef(fmaf(eku, vq.z, stA), stB + eku);
            stA  = fmaf(lam, stA, uA2);  stB = fmaf(lam, stB, ek2);
            eku  = eu * ek3;
            yq.w = __fdividef(fmaf(eku, vq.w, stA), stB + eku);

            // Stage y: one STS.128, conflict-free.
            *reinterpret_cast<float4*>(sy + w * STR + 4 * lane) = yq;

            // Next-chunk seed from lane 31's inclusive totals.
            const float LA = __shfl_sync(FULL, IA, 31);
            const float LB = __shfl_sync(FULL, IB, 31);
            SA = fmaf(lam128, SA, LA);
            SB = fmaf(lam128, SB, LB);

            // ---- fill next buffer from registers, fetch tile+2 ----
            if (ti + 1 < ntiles) sts_tile((ti + 1) & 1);
            if (ti + 2 < ntiles) ldg_tile(ti + 2);
            __syncthreads();        // y staged + next k/v buffer complete

            // ---- flush y: gather [c][t] -> [t][c], STG.128 ----
            const int gt = t0 + lt;
            if (gt < T) {
                float4 yo;
                yo.x = sy[(cg * 4 + 0) * STR + lt];
                yo.y = sy[(cg * 4 + 1) * STR + lt];
                yo.z = sy[(cg * 4 + 2) * STR + lt];
                yo.w = sy[(cg * 4 + 3) * STR + lt];
                const int gc = c0 + cg * 4;
                if (vec_ok) {
                    stcs4(ob + (long long)gt * C + gc, yo);
                } else {
                    if (gc + 0 < C) stcs(ob + (long long)gt * C + gc + 0, yo.x);
                    if (gc + 1 < C) stcs(ob + (long long)gt * C + gc + 1, yo.y);
                    if (gc + 2 < C) stcs(ob + (long long)gt * C + gc + 2, yo.z);
                    if (gc + 3 < C) stcs(ob + (long long)gt * C + gc + 3, yo.w);
                }
            }
            __syncthreads();        // sy free for next iteration
        }
    }
}

extern "C" void kernel_launch(void* const* d_in, const int* in_sizes, int n_in,
                              void* d_out, int out_size)
{
    // metadata order: batch_size, seq_len, embedding_dim, time_decay,
    //                 time_first, k, v
    const void*  seqlen_p = d_in[1];
    const float* td = (const float*)d_in[3];
    const float* tf = (const float*)d_in[4];
    const float* k  = (const float*)d_in[5];
    const float* v  = (const float*)d_in[6];
    float* out = (float*)d_out;

    const int C = in_sizes[3];
    const long long BTC = in_sizes[5];

    static bool attr_done = false;
    if (!attr_done) {
        cudaFuncSetAttribute(wkv_warpscan_kernel,
                             cudaFuncAttributeMaxDynamicSharedMemorySize,
                             SMEM_BYTES);
        attr_done = true;
    }

    wkv_warpscan_kernel<<<GRID, THREADS, SMEM_BYTES>>>(
        seqlen_p, td, tf, k, v, out, C, BTC);
}

// round 16
// speedup vs baseline: 1.1322x; 1.1322x over previous
#include <cuda_runtime.h>
#include <cstdint>

// WKV (RWKV v4) — warp-parallel weighted scan, thread-serial-4 (R13 config,
// the measured best) + Montgomery batched reciprocal to break the MUFU wall.
//
//   state_t = lam*state_{t-1} + e^{k_t}(v_t, 1),  lam = exp(-exp(td[c]))
//   y_t = (A_{t-1} + e^u e^{k_t} v_t) / (B_{t-1} + e^u e^{k_t})
//
// R11-R15 all plateaued at ~60us with nothing saturated in ncu's summary.
// Op count shows why: 2 MUFU/element (EX2 + RCP) x 113K elements/SM at
// ~2 MUFU/cyc/SM = ~59us = the plateau. This kernel batches the 4 per-thread
// divisions into ONE rcp.approx (prefix-product unwind on the FMA pipe,
// which has headroom): 1.25 MUFU/element -> ~37us compute bound.
// Everything else identical to R13: block = 512 thr = 16 warps = 16
// channels; thread owns 4 consecutive t; smem [16][132] channel-major
// (conflict-free LDS.128 scan / STS.128 stage; 2-way transpose);
// LDG.128->reg->STS pipelined; single pass (192 MB floor).

constexpr int CPB     = 16;           // channels per block == warps
constexpr int TS      = 128;          // timesteps per tile
constexpr int STR     = 132;          // floats per channel row (16B-aligned)
constexpr int THREADS = 512;
constexpr int GRID    = 1024;
constexpr int ARR_F   = CPB * STR;    // floats per array buffer
// smem: k[2] | v[2] | y[1]
constexpr int SMEM_BYTES = 5 * ARR_F * (int)sizeof(float);  // 42240 B

__device__ __forceinline__ void stcs4(float* p, float4 v) {
    asm volatile("st.global.cs.v4.f32 [%0], {%1, %2, %3, %4};\n"
                 :: "l"(p), "f"(v.x), "f"(v.y), "f"(v.z), "f"(v.w) : "memory");
}
__device__ __forceinline__ void stcs(float* p, float v) {
    asm volatile("st.global.cs.f32 [%0], %1;\n" :: "l"(p), "f"(v) : "memory");
}
__device__ __forceinline__ float4 ldcs4(const float* p) {
    float4 v;
    asm volatile("ld.global.cs.v4.f32 {%0, %1, %2, %3}, [%4];\n"
                 : "=f"(v.x), "=f"(v.y), "=f"(v.z), "=f"(v.w) : "l"(p));
    return v;
}
__device__ __forceinline__ float frcp(float x) {   // MUFU rcp.approx
    float r;
    asm("rcp.approx.ftz.f32 %0, %1;" : "=f"(r) : "f"(x));
    return r;
}

__device__ __forceinline__ int read_dim(const void* p) {
    int i = *reinterpret_cast<const int*>(p);
    if (i >= 1 && i <= (1 << 20)) return i;
    float f = *reinterpret_cast<const float*>(p);
    int fi = (int)f;
    return (fi >= 1) ? fi : 1;
}

__global__ __launch_bounds__(THREADS, 2)
void wkv_warpscan_kernel(const void* __restrict__ seqlen_p,
                         const float* __restrict__ td,
                         const float* __restrict__ tf,
                         const float* __restrict__ kg,
                         const float* __restrict__ vg,
                         float* __restrict__ out,
                         int C, long long BTC)
{
    extern __shared__ float smem[];
    float* skb[2] = { smem,              smem + ARR_F };
    float* svb[2] = { smem + 2 * ARR_F,  smem + 3 * ARR_F };
    float* sy     =   smem + 4 * ARR_F;

    const int tid  = threadIdx.x;
    const int w    = tid >> 5;        // warp == local channel
    const int lane = tid & 31;
    const int lt   = tid >> 2;        // 0..127 : timestep row for ld/st
    const int cg   = tid & 3;         // 0..3   : 4-channel group

    const int T = read_dim(seqlen_p);
    const long long BT = BTC / C;
    const int B = (int)(BT / T);
    const int ctiles = (C + CPB - 1) / CPB;
    const int nrows  = B * ctiles;
    const int ntiles = (T + TS - 1) / TS;
    const unsigned FULL = 0xffffffffu;

    const bool vec_ok = ((C & 15) == 0) &&
                        ((((uintptr_t)kg)  & 15) == 0) &&
                        ((((uintptr_t)vg)  & 15) == 0) &&
                        ((((uintptr_t)out) & 15) == 0);

    for (int row = blockIdx.x; row < nrows; row += gridDim.x) {
        const int b  = row / ctiles;
        const int c0 = (row % ctiles) * CPB;
        const float* kb = kg + (long long)b * T * C;
        const float* vb = vg + (long long)b * T * C;
        float* ob = out + (long long)b * T * C;

        const int  c      = c0 + w;
        const bool cvalid = (c < C);
        const float ew  = cvalid ? __expf(td[c]) : 0.f;   // e^{td}
        const float eu  = cvalid ? __expf(tf[c]) : 0.f;   // e^{tf}
        const float lam = __expf(-ew);                    // exp(-e^{td})
        const float l2   = lam * lam;
        const float lam4 = l2 * l2;                       // KS base weight
        const float w1 = lam4, w2 = w1 * w1, w4 = w2 * w2,
                    w8 = w4 * w4, w16 = w8 * w8;
        const float lam128 = w16 * w16;                   // lam^128
        const float lam4lane = __expf(-4.f * (float)lane * ew);  // lam^{4lane}

        float SA = 0.f, SB = 0.f;                         // running seed

        float4 kR, vR;                                    // staged next tile

        auto ldg_tile = [&](int ti) {
            int gt = ti * TS + lt; if (gt >= T) gt = T - 1;
            if (vec_ok) {
                const long long go = (long long)gt * C + c0 + cg * 4;
                kR = ldcs4(kb + go);
                vR = ldcs4(vb + go);
            } else {
                float kk[4], vv[4];
                #pragma unroll
                for (int i = 0; i < 4; ++i) {
                    const int gc = c0 + cg * 4 + i;
                    kk[i] = (gc < C) ? kb[(long long)gt * C + gc] : 0.f;
                    vv[i] = (gc < C) ? vb[(long long)gt * C + gc] : 0.f;
                }
                kR = make_float4(kk[0], kk[1], kk[2], kk[3]);
                vR = make_float4(vv[0], vv[1], vv[2], vv[3]);
            }
        };
        auto sts_tile = [&](int buf) {  // transpose registers -> [c][t]
            float* dk = skb[buf];
            float* dv = svb[buf];
            dk[(cg * 4 + 0) * STR + lt] = kR.x;
            dk[(cg * 4 + 1) * STR + lt] = kR.y;
            dk[(cg * 4 + 2) * STR + lt] = kR.z;
            dk[(cg * 4 + 3) * STR + lt] = kR.w;
            dv[(cg * 4 + 0) * STR + lt] = vR.x;
            dv[(cg * 4 + 1) * STR + lt] = vR.y;
            dv[(cg * 4 + 2) * STR + lt] = vR.z;
            dv[(cg * 4 + 3) * STR + lt] = vR.w;
        };

        // ---- prolog: fill buffer 0, stage tile 1 in registers ----
        ldg_tile(0);
        sts_tile(0);
        if (ntiles > 1) ldg_tile(1);
        __syncthreads();

        for (int ti = 0; ti < ntiles; ++ti) {
            const int buf = ti & 1;
            const int t0  = ti * TS;

            // ---- scan: one LDS.128 per array, conflict-free ----
            const float* tk = skb[buf] + w * STR + 4 * lane;
            const float* tv = svb[buf] + w * STR + 4 * lane;
            const float4 kq = *reinterpret_cast<const float4*>(tk);
            const float4 vq = *reinterpret_cast<const float4*>(tv);

            const int tg = t0 + 4 * lane;
            const bool v0 = cvalid && (tg + 0 < T);
            const bool v1 = cvalid && (tg + 1 < T);
            const bool v2 = cvalid && (tg + 2 < T);
            const bool v3 = cvalid && (tg + 3 < T);
            const float ek0 = v0 ? __expf(kq.x) : 0.f;
            const float ek1 = v1 ? __expf(kq.y) : 0.f;
            const float ek2 = v2 ? __expf(kq.z) : 0.f;
            const float ek3 = v3 ? __expf(kq.w) : 0.f;
            const float uA0 = ek0 * vq.x, uA1 = ek1 * vq.y;
            const float uA2 = ek2 * vq.z, uA3 = ek3 * vq.w;

            // Thread-local inclusive totals (4 steps).
            float IA = uA0, IB = ek0;
            IA = fmaf(lam, IA, uA1);  IB = fmaf(lam, IB, ek1);
            IA = fmaf(lam, IA, uA2);  IB = fmaf(lam, IB, ek2);
            IA = fmaf(lam, IA, uA3);  IB = fmaf(lam, IB, ek3);

            // Kogge-Stone over lanes, weight lam^4.
            float a, bb;
            a = __shfl_up_sync(FULL, IA, 1);  bb = __shfl_up_sync(FULL, IB, 1);
            if (lane >= 1)  { IA = fmaf(w1,  a, IA); IB = fmaf(w1,  bb, IB); }
            a = __shfl_up_sync(FULL, IA, 2);  bb = __shfl_up_sync(FULL, IB, 2);
            if (lane >= 2)  { IA = fmaf(w2,  a, IA); IB = fmaf(w2,  bb, IB); }
            a = __shfl_up_sync(FULL, IA, 4);  bb = __shfl_up_sync(FULL, IB, 4);
            if (lane >= 4)  { IA = fmaf(w4,  a, IA); IB = fmaf(w4,  bb, IB); }
            a = __shfl_up_sync(FULL, IA, 8);  bb = __shfl_up_sync(FULL, IB, 8);
            if (lane >= 8)  { IA = fmaf(w8,  a, IA); IB = fmaf(w8,  bb, IB); }
            a = __shfl_up_sync(FULL, IA, 16); bb = __shfl_up_sync(FULL, IB, 16);
            if (lane >= 16) { IA = fmaf(w16, a, IA); IB = fmaf(w16, bb, IB); }

            float EA = __shfl_up_sync(FULL, IA, 1);
            float EB = __shfl_up_sync(FULL, IB, 1);
            if (lane == 0) { EA = 0.f; EB = 0.f; }

            // State just before this thread's first element.
            float stA = fmaf(lam4lane, SA, EA);
            float stB = fmaf(lam4lane, SB, EB);

            // ---- emit 4 timesteps: gather numerators/denominators, then
            //      ONE rcp.approx + prefix-product unwind (Montgomery). ----
            float n0, n1, n2, n3, d0, d1, d2, d3, eku;
            eku = eu * ek0;
            n0  = fmaf(eku, vq.x, stA);  d0 = v0 ? (stB + eku) : 1.f;
            stA = fmaf(lam, stA, uA0);   stB = fmaf(lam, stB, ek0);
            eku = eu * ek1;
            n1  = fmaf(eku, vq.y, stA);  d1 = v1 ? (stB + eku) : 1.f;
            stA = fmaf(lam, stA, uA1);   stB = fmaf(lam, stB, ek1);
            eku = eu * ek2;
            n2  = fmaf(eku, vq.z, stA);  d2 = v2 ? (stB + eku) : 1.f;
            stA = fmaf(lam, stA, uA2);   stB = fmaf(lam, stB, ek2);
            eku = eu * ek3;
            n3  = fmaf(eku, vq.w, stA);  d3 = v3 ? (stB + eku) : 1.f;

            const float p01  = d0 * d1;
            const float p012 = p01 * d2;
            const float r    = frcp(p012 * d3);   // 1/(d0 d1 d2 d3)
            float4 yq;
            yq.w = n3 * r * p012;                 // n3/d3
            const float r012 = r * d3;            // 1/(d0 d1 d2)
            yq.z = n2 * r012 * p01;               // n2/d2
            const float r01  = r012 * d2;         // 1/(d0 d1)
            yq.y = n1 * r01 * d0;                 // n1/d1
            yq.x = n0 * (r01 * d1);               // n0/d0

            // Stage y: one STS.128, conflict-free.
            *reinterpret_cast<float4*>(sy + w * STR + 4 * lane) = yq;

            // Next-chunk seed from lane 31's inclusive totals.
            const float LA = __shfl_sync(FULL, IA, 31);
            const float LB = __shfl_sync(FULL, IB, 31);
            SA = fmaf(lam128, SA, LA);
            SB = fmaf(lam128, SB, LB);

            // ---- fill next buffer from registers, fetch tile+2 ----
            if (ti + 1 < ntiles) sts_tile((ti + 1) & 1);
            if (ti + 2 < ntiles) ldg_tile(ti + 2);
            __syncthreads();        // y staged + next k/v buffer complete

            // ---- flush y: gather [c][t] -> [t][c], STG.128 ----
            const int gt = t0 + lt;
            if (gt < T) {
                float4 yo;
                yo.x = sy[(cg * 4 + 0) * STR + lt];
                yo.y = sy[(cg * 4 + 1) * STR + lt];
                yo.z = sy[(cg * 4 + 2) * STR + lt];
                yo.w = sy[(cg * 4 + 3) * STR + lt];
                const int gc = c0 + cg * 4;
                if (vec_ok) {
                    stcs4(ob + (long long)gt * C + gc, yo);
                } else {
                    if (gc + 0 < C) stcs(ob + (long long)gt * C + gc + 0, yo.x);
                    if (gc + 1 < C) stcs(ob + (long long)gt * C + gc + 1, yo.y);
                    if (gc + 2 < C) stcs(ob + (long long)gt * C + gc + 2, yo.z);
                    if (gc + 3 < C) stcs(ob + (long long)gt * C + gc + 3, yo.w);
                }
            }
            __syncthreads();        // sy free for next iteration
        }
    }
}

extern "C" void kernel_launch(void* const* d_in, const int* in_sizes, int n_in,
                              void* d_out, int out_size)
{
    // metadata order: batch_size, seq_len, embedding_dim, time_decay,
    //                 time_first, k, v
    const void*  seqlen_p = d_in[1];
    const float* td = (const float*)d_in[3];
    const float* tf = (const float*)d_in[4];
    const float* k  = (const float*)d_in[5];
    const float* v  = (const float*)d_in[6];
    float* out = (float*)d_out;

    const int C = in_sizes[3];
    const long long BTC = in_sizes[5];

    static bool attr_done = false;
    if (!attr_done) {
        cudaFuncSetAttribute(wkv_warpscan_kernel,
                             cudaFuncAttributeMaxDynamicSharedMemorySize,
                             SMEM_BYTES);
        attr_done = true;
    }

    wkv_warpscan_kernel<<<GRID, THREADS, SMEM_BYTES>>>(
        seqlen_p, td, tf, k, v, out, C, BTC);
}

// round 17
// speedup vs baseline: 1.1660x; 1.0298x over previous
#include <cuda_runtime.h>
#include <cstdint>

// WKV (RWKV v4) — warp-parallel weighted scan, thread-serial-4 (R13/R16
// structure) with occupancy raised from 32 to 48 warps/SM.
//
//   state_t = lam*state_{t-1} + e^{k_t}(v_t, 1),  lam = exp(-exp(td[c]))
//   y_t = (A_{t-1} + e^u e^{k_t} v_t) / (B_{t-1} + e^u e^{k_t})
//
// R11-R16 finding: every variant plateaued at ~60-70us with exactly 32
// warps/SM resident — the 64 reg/thread compile capped residency at
// 65536/64 = 1024 threads/SM regardless of smem config, and with nothing
// saturated (DRAM 35%, issue 54%) the kernels are latency-bound at that
// warp count. __launch_bounds__(512, 3) forces regs <= 42 -> 3 blocks x
// 16 warps = 48 warps/SM (75% occ), +50% latency hiding / load streams.
// Everything else identical to R16 (best: 61.9us): block = 16 warps = 16
// channels, thread owns 4 consecutive t, smem [16][132] channel-major
// (conflict-free LDS.128/STS.128, 2-way transpose), LDG.128 pipelined,
// Montgomery batched reciprocal, single pass (192 MB floor).

constexpr int CPB     = 16;           // channels per block == warps
constexpr int TS      = 128;          // timesteps per tile
constexpr int STR     = 132;          // floats per channel row (16B-aligned)
constexpr int THREADS = 512;
constexpr int GRID    = 1024;
constexpr int ARR_F   = CPB * STR;    // floats per array buffer
// smem: k[2] | v[2] | y[1]
constexpr int SMEM_BYTES = 5 * ARR_F * (int)sizeof(float);  // 42240 B

__device__ __forceinline__ void stcs4(float* p, float4 v) {
    asm volatile("st.global.cs.v4.f32 [%0], {%1, %2, %3, %4};\n"
                 :: "l"(p), "f"(v.x), "f"(v.y), "f"(v.z), "f"(v.w) : "memory");
}
__device__ __forceinline__ void stcs(float* p, float v) {
    asm volatile("st.global.cs.f32 [%0], %1;\n" :: "l"(p), "f"(v) : "memory");
}
__device__ __forceinline__ float4 ldcs4(const float* p) {
    float4 v;
    asm volatile("ld.global.cs.v4.f32 {%0, %1, %2, %3}, [%4];\n"
                 : "=f"(v.x), "=f"(v.y), "=f"(v.z), "=f"(v.w) : "l"(p));
    return v;
}
__device__ __forceinline__ float frcp(float x) {   // MUFU rcp.approx
    float r;
    asm("rcp.approx.ftz.f32 %0, %1;" : "=f"(r) : "f"(x));
    return r;
}

__device__ __forceinline__ int read_dim(const void* p) {
    int i = *reinterpret_cast<const int*>(p);
    if (i >= 1 && i <= (1 << 20)) return i;
    float f = *reinterpret_cast<const float*>(p);
    int fi = (int)f;
    return (fi >= 1) ? fi : 1;
}

__global__ __launch_bounds__(THREADS, 3)
void wkv_warpscan_kernel(const void* __restrict__ seqlen_p,
                         const float* __restrict__ td,
                         const float* __restrict__ tf,
                         const float* __restrict__ kg,
                         const float* __restrict__ vg,
                         float* __restrict__ out,
                         int C, long long BTC)
{
    extern __shared__ float smem[];
    float* skb[2] = { smem,              smem + ARR_F };
    float* svb[2] = { smem + 2 * ARR_F,  smem + 3 * ARR_F };
    float* sy     =   smem + 4 * ARR_F;

    const int tid  = threadIdx.x;
    const int w    = tid >> 5;        // warp == local channel
    const int lane = tid & 31;
    const int lt   = tid >> 2;        // 0..127 : timestep row for ld/st
    const int cg   = tid & 3;         // 0..3   : 4-channel group

    const int T = read_dim(seqlen_p);
    const long long BT = BTC / C;
    const int B = (int)(BT / T);
    const int ctiles = (C + CPB - 1) / CPB;
    const int nrows  = B * ctiles;
    const int ntiles = (T + TS - 1) / TS;
    const unsigned FULL = 0xffffffffu;

    const bool vec_ok = ((C & 15) == 0) &&
                        ((((uintptr_t)kg)  & 15) == 0) &&
                        ((((uintptr_t)vg)  & 15) == 0) &&
                        ((((uintptr_t)out) & 15) == 0);

    for (int row = blockIdx.x; row < nrows; row += gridDim.x) {
        const int b  = row / ctiles;
        const int c0 = (row % ctiles) * CPB;
        const float* kb = kg + (long long)b * T * C;
        const float* vb = vg + (long long)b * T * C;
        float* ob = out + (long long)b * T * C;

        const int  c      = c0 + w;
        const bool cvalid = (c < C);
        const float ew  = cvalid ? __expf(td[c]) : 0.f;   // e^{td}
        const float eu  = cvalid ? __expf(tf[c]) : 0.f;   // e^{tf}
        const float lam = __expf(-ew);                    // exp(-e^{td})
        const float l2   = lam * lam;
        const float lam4 = l2 * l2;                       // KS base weight
        const float w1 = lam4, w2 = w1 * w1, w4 = w2 * w2,
                    w8 = w4 * w4, w16 = w8 * w8;
        const float lam128 = w16 * w16;                   // lam^128
        const float lam4lane = __expf(-4.f * (float)lane * ew);  // lam^{4lane}

        float SA = 0.f, SB = 0.f;                         // running seed

        float4 kR, vR;                                    // staged next tile

        auto ldg_tile = [&](int ti) {
            int gt = ti * TS + lt; if (gt >= T) gt = T - 1;
            if (vec_ok) {
                const long long go = (long long)gt * C + c0 + cg * 4;
                kR = ldcs4(kb + go);
                vR = ldcs4(vb + go);
            } else {
                float kk[4], vv[4];
                #pragma unroll
                for (int i = 0; i < 4; ++i) {
                    const int gc = c0 + cg * 4 + i;
                    kk[i] = (gc < C) ? kb[(long long)gt * C + gc] : 0.f;
                    vv[i] = (gc < C) ? vb[(long long)gt * C + gc] : 0.f;
                }
                kR = make_float4(kk[0], kk[1], kk[2], kk[3]);
                vR = make_float4(vv[0], vv[1], vv[2], vv[3]);
            }
        };
        auto sts_tile = [&](int buf) {  // transpose registers -> [c][t]
            float* dk = skb[buf];
            float* dv = svb[buf];
            dk[(cg * 4 + 0) * STR + lt] = kR.x;
            dk[(cg * 4 + 1) * STR + lt] = kR.y;
            dk[(cg * 4 + 2) * STR + lt] = kR.z;
            dk[(cg * 4 + 3) * STR + lt] = kR.w;
            dv[(cg * 4 + 0) * STR + lt] = vR.x;
            dv[(cg * 4 + 1) * STR + lt] = vR.y;
            dv[(cg * 4 + 2) * STR + lt] = vR.z;
            dv[(cg * 4 + 3) * STR + lt] = vR.w;
        };

        // ---- prolog: fill buffer 0, stage tile 1 in registers ----
        ldg_tile(0);
        sts_tile(0);
        if (ntiles > 1) ldg_tile(1);
        __syncthreads();

        for (int ti = 0; ti < ntiles; ++ti) {
            const int buf = ti & 1;
            const int t0  = ti * TS;

            // ---- scan: one LDS.128 per array, conflict-free ----
            const float* tk = skb[buf] + w * STR + 4 * lane;
            const float* tv = svb[buf] + w * STR + 4 * lane;
            const float4 kq = *reinterpret_cast<const float4*>(tk);
            const float4 vq = *reinterpret_cast<const float4*>(tv);

            const int tg = t0 + 4 * lane;
            const bool v0 = cvalid && (tg + 0 < T);
            const bool v1 = cvalid && (tg + 1 < T);
            const bool v2 = cvalid && (tg + 2 < T);
            const bool v3 = cvalid && (tg + 3 < T);
            const float ek0 = v0 ? __expf(kq.x) : 0.f;
            const float ek1 = v1 ? __expf(kq.y) : 0.f;
            const float ek2 = v2 ? __expf(kq.z) : 0.f;
            const float ek3 = v3 ? __expf(kq.w) : 0.f;
            const float uA0 = ek0 * vq.x, uA1 = ek1 * vq.y;
            const float uA2 = ek2 * vq.z, uA3 = ek3 * vq.w;

            // Thread-local inclusive totals (4 steps).
            float IA = uA0, IB = ek0;
            IA = fmaf(lam, IA, uA1);  IB = fmaf(lam, IB, ek1);
            IA = fmaf(lam, IA, uA2);  IB = fmaf(lam, IB, ek2);
            IA = fmaf(lam, IA, uA3);  IB = fmaf(lam, IB, ek3);

            // Kogge-Stone over lanes, weight lam^4.
            float a, bb;
            a = __shfl_up_sync(FULL, IA, 1);  bb = __shfl_up_sync(FULL, IB, 1);
            if (lane >= 1)  { IA = fmaf(w1,  a, IA); IB = fmaf(w1,  bb, IB); }
            a = __shfl_up_sync(FULL, IA, 2);  bb = __shfl_up_sync(FULL, IB, 2);
            if (lane >= 2)  { IA = fmaf(w2,  a, IA); IB = fmaf(w2,  bb, IB); }
            a = __shfl_up_sync(FULL, IA, 4);  bb = __shfl_up_sync(FULL, IB, 4);
            if (lane >= 4)  { IA = fmaf(w4,  a, IA); IB = fmaf(w4,  bb, IB); }
            a = __shfl_up_sync(FULL, IA, 8);  bb = __shfl_up_sync(FULL, IB, 8);
            if (lane >= 8)  { IA = fmaf(w8,  a, IA); IB = fmaf(w8,  bb, IB); }
            a = __shfl_up_sync(FULL, IA, 16); bb = __shfl_up_sync(FULL, IB, 16);
            if (lane >= 16) { IA = fmaf(w16, a, IA); IB = fmaf(w16, bb, IB); }

            float EA = __shfl_up_sync(FULL, IA, 1);
            float EB = __shfl_up_sync(FULL, IB, 1);
            if (lane == 0) { EA = 0.f; EB = 0.f; }

            // State just before this thread's first element.
            float stA = fmaf(lam4lane, SA, EA);
            float stB = fmaf(lam4lane, SB, EB);

            // ---- emit 4 timesteps: ONE rcp.approx + prefix-product unwind ----
            float n0, n1, n2, n3, d0, d1, d2, d3, eku;
            eku = eu * ek0;
            n0  = fmaf(eku, vq.x, stA);  d0 = v0 ? (stB + eku) : 1.f;
            stA = fmaf(lam, stA, uA0);   stB = fmaf(lam, stB, ek0);
            eku = eu * ek1;
            n1  = fmaf(eku, vq.y, stA);  d1 = v1 ? (stB + eku) : 1.f;
            stA = fmaf(lam, stA, uA1);   stB = fmaf(lam, stB, ek1);
            eku = eu * ek2;
            n2  = fmaf(eku, vq.z, stA);  d2 = v2 ? (stB + eku) : 1.f;
            stA = fmaf(lam, stA, uA2);   stB = fmaf(lam, stB, ek2);
            eku = eu * ek3;
            n3  = fmaf(eku, vq.w, stA);  d3 = v3 ? (stB + eku) : 1.f;

            const float p01  = d0 * d1;
            const float p012 = p01 * d2;
            const float r    = frcp(p012 * d3);   // 1/(d0 d1 d2 d3)
            float4 yq;
            yq.w = n3 * r * p012;                 // n3/d3
            const float r012 = r * d3;            // 1/(d0 d1 d2)
            yq.z = n2 * r012 * p01;               // n2/d2
            const float r01  = r012 * d2;         // 1/(d0 d1)
            yq.y = n1 * r01 * d0;                 // n1/d1
            yq.x = n0 * (r01 * d1);               // n0/d0

            // Stage y: one STS.128, conflict-free.
            *reinterpret_cast<float4*>(sy + w * STR + 4 * lane) = yq;

            // Next-chunk seed from lane 31's inclusive totals.
            const float LA = __shfl_sync(FULL, IA, 31);
            const float LB = __shfl_sync(FULL, IB, 31);
            SA = fmaf(lam128, SA, LA);
            SB = fmaf(lam128, SB, LB);

            // ---- fill next buffer from registers, fetch tile+2 ----
            if (ti + 1 < ntiles) sts_tile((ti + 1) & 1);
            if (ti + 2 < ntiles) ldg_tile(ti + 2);
            __syncthreads();        // y staged + next k/v buffer complete

            // ---- flush y: gather [c][t] -> [t][c], STG.128 ----
            const int gt = t0 + lt;
            if (gt < T) {
                float4 yo;
                yo.x = sy[(cg * 4 + 0) * STR + lt];
                yo.y = sy[(cg * 4 + 1) * STR + lt];
                yo.z = sy[(cg * 4 + 2) * STR + lt];
                yo.w = sy[(cg * 4 + 3) * STR + lt];
                const int gc = c0 + cg * 4;
                if (vec_ok) {
                    stcs4(ob + (long long)gt * C + gc, yo);
                } else {
                    if (gc + 0 < C) stcs(ob + (long long)gt * C + gc + 0, yo.x);
                    if (gc + 1 < C) stcs(ob + (long long)gt * C + gc + 1, yo.y);
                    if (gc + 2 < C) stcs(ob + (long long)gt * C + gc + 2, yo.z);
                    if (gc + 3 < C) stcs(ob + (long long)gt * C + gc + 3, yo.w);
                }
            }
            __syncthreads();        // sy free for next iteration
        }
    }
}

extern "C" void kernel_launch(void* const* d_in, const int* in_sizes, int n_in,
                              void* d_out, int out_size)
{
    // metadata order: batch_size, seq_len, embedding_dim, time_decay,
    //                 time_first, k, v
    const void*  seqlen_p = d_in[1];
    const float* td = (const float*)d_in[3];
    const float* tf = (const float*)d_in[4];
    const float* k  = (const float*)d_in[5];
    const float* v  = (const float*)d_in[6];
    float* out = (float*)d_out;

    const int C = in_sizes[3];
    const long long BTC = in_sizes[5];

    static bool attr_done = false;
    if (!attr_done) {
        cudaFuncSetAttribute(wkv_warpscan_kernel,
                             cudaFuncAttributeMaxDynamicSharedMemorySize,
                             SMEM_BYTES);
        attr_done = true;
    }

    wkv_warpscan_kernel<<<GRID, THREADS, SMEM_BYTES>>>(
        seqlen_p, td, tf, k, v, out, C, BTC);
}